// round 1
// baseline (speedup 1.0000x reference)
#include <cuda_runtime.h>
#include <cstdint>

#define F_FIELDS 17
#define HH 300
#define WW 400
#define H_F 38
#define W_F 50
#define NPTS (H_F * W_F)              /* 1900 points per field */
#define NPOINTS (F_FIELDS * NPTS)     /* 32300 total points    */
#define RAD 13
#define WIN (2 * RAD + 1)             /* 27 */
#define V_TH 0.1f
#define OUT_ELEMS (F_FIELDS * HH * WW) /* 2,040,000 */

// One warp per point. Lanes 0..26 own window columns; warp loops 27 rows
// with early rejection of rows outside bounds or outside the 2*sigma trunc.
__global__ void __launch_bounds__(256) cifhr_accum_kernel(
    const float* __restrict__ x, float* __restrict__ out)
{
    const int gtid   = blockIdx.x * blockDim.x + threadIdx.x;
    const int warpId = gtid >> 5;
    const int lane   = gtid & 31;
    if (warpId >= NPOINTS) return;

    const int f = warpId / NPTS;
    const int p = warpId - f * NPTS;

    // x layout: (F, 5, H_F, W_F); channel stride = NPTS
    const float* base = x + ((size_t)f * 5) * NPTS + p;
    const float v = base[0];
    const float scale = base[4 * NPTS];
    // valid = v >= V_TH && scale*STRIDE >= MIN_SCALE (MIN_SCALE = 0)
    if (!(v >= V_TH) || !(scale * 8.0f >= 0.0f)) return;

    const float px = base[NPTS] * 8.0f;
    const float py = base[2 * NPTS] * 8.0f;

    const float sigma  = fmaxf(1.0f, 4.0f * scale);
    const float sigma2 = sigma * sigma;
    const float trunc2 = 4.0f * sigma2;
    const float value  = v * (1.0f / 16.0f);         /* v / NEIGHBORS * FACTOR */
    const float inv8   = -0.0625f / sigma2;          /* (-0.5/sigma2) / 8      */

    const int cx = (int)rintf(px);                   /* round-half-even, matches jnp.round */
    const int cy = (int)rintf(py);

    // Per-lane column
    const int   xi    = cx - RAD + lane;
    const float dx    = (float)xi - px;
    const float dx2   = dx * dx;
    const bool  xok   = (lane < WIN) && (xi >= 0) && (xi < WW) && (dx2 <= trunc2);
    const bool  nearx = dx2 < 0.25f;

    float* __restrict__ fbase = out + (size_t)f * (HH * WW);

    #pragma unroll 1
    for (int r = 0; r < WIN; ++r) {
        const int yi = cy - RAD + r;
        if (yi < 0 || yi >= HH) continue;
        const float dy  = (float)yi - py;
        const float dy2 = dy * dy;
        if (dy2 > trunc2) continue;                  /* whole row truncated */

        const float d2 = dy2 + dx2;
        if (xok && d2 <= trunc2) {
            float g;
            if (nearx && dy2 < 0.25f) {
                g = 1.0f;
            } else {
                float t = fmaf(d2, inv8, 1.0f);      /* 1 + x/8, x = -0.5*d2/sigma2 */
                t = t * t;
                t = t * t;
                t = t * t;                           /* (1+x/8)^8 */
                g = t;
            }
            atomicAdd(&fbase[yi * WW + xi], value * g);
        }
    }
}

__global__ void __launch_bounds__(256) cifhr_clamp_kernel(float* __restrict__ out)
{
    const int i = blockIdx.x * blockDim.x + threadIdx.x;
    const int n4 = OUT_ELEMS / 4;
    if (i >= n4) return;
    float4 val = ((float4*)out)[i];
    val.x = fminf(val.x, 1.0f);
    val.y = fminf(val.y, 1.0f);
    val.z = fminf(val.z, 1.0f);
    val.w = fminf(val.w, 1.0f);
    ((float4*)out)[i] = val;
}

extern "C" void kernel_launch(void* const* d_in, const int* in_sizes, int n_in,
                              void* d_out, int out_size)
{
    const float* cifhr = (const float*)d_in[0];   /* (17,300,400) float32 */
    const float* x     = (const float*)d_in[1];   /* (17,5,38,50)  float32 */
    float* out = (float*)d_out;

    // out starts as cifhr (all zeros in this problem, but keep it general)
    cudaMemcpyAsync(out, cifhr, (size_t)OUT_ELEMS * sizeof(float),
                    cudaMemcpyDeviceToDevice, 0);

    // One warp per point
    const int threads = NPOINTS * 32;
    const int block = 256;
    const int grid = (threads + block - 1) / block;
    cifhr_accum_kernel<<<grid, block, 0, 0>>>(x, out);

    const int n4 = OUT_ELEMS / 4;
    cifhr_clamp_kernel<<<(n4 + 255) / 256, 256, 0, 0>>>(out);
}

// round 2
// speedup vs baseline: 1.2749x; 1.2749x over previous
#include <cuda_runtime.h>
#include <cstdint>

#define F_FIELDS 17
#define HH 300
#define WW 400
#define H_F 38
#define W_F 50
#define NPTS (H_F * W_F)              /* 1900 points per field */
#define NPOINTS (F_FIELDS * NPTS)     /* 32300 total points    */
#define RAD 13
#define WIN (2 * RAD + 1)             /* 27 */
#define V_TH 0.1f
#define OUT_ELEMS (F_FIELDS * HH * WW) /* 2,040,000 */

// One warp per point. Lane layout: slot = lane&7 (aligned 4-column group),
// rsub = lane>>3 (row sub-index). 7 iterations x 4 rows cover the 27 window
// rows. Each lane packs 4 masked contributions into ONE float4 RED
// (RED.E.ADD.128) -> ~4x fewer LSU atomic ops than scalar REDs.
__global__ void __launch_bounds__(256) cifhr_accum_kernel(
    const float* __restrict__ x, float* __restrict__ out)
{
    const int gtid   = blockIdx.x * blockDim.x + threadIdx.x;
    const int warpId = gtid >> 5;
    const int lane   = gtid & 31;
    if (warpId >= NPOINTS) return;

    const int f = warpId / NPTS;
    const int p = warpId - f * NPTS;

    // x layout: (F, 5, H_F, W_F); channel stride = NPTS
    const float* base = x + ((size_t)f * 5) * NPTS + p;
    const float v = base[0];
    const float scale = base[4 * NPTS];
    if (!(v >= V_TH) || !(scale * 8.0f >= 0.0f)) return;

    const float px = base[NPTS] * 8.0f;
    const float py = base[2 * NPTS] * 8.0f;

    const float sigma  = fmaxf(1.0f, 4.0f * scale);
    const float sigma2 = sigma * sigma;
    const float trunc2 = 4.0f * sigma2;
    const float value  = v * (1.0f / 16.0f);         /* v / NEIGHBORS * FACTOR */
    const float inv8   = -0.0625f / sigma2;          /* (-0.5/sigma2) / 8      */

    const int cx = (int)rintf(px);                   /* round-half-even, matches jnp.round */
    const int cy = (int)rintf(py);

    // Aligned 4-column slots covering [cx-13, cx+13]. slot0 is a multiple of
    // 4 (floor even for negatives via & ~3 on two's complement).
    const int slot0 = (cx - RAD) & ~3;
    const int slot  = lane & 7;          /* 0..7  */
    const int rsub  = lane >> 3;         /* 0..3  */
    const int colb  = slot0 + slot * 4;  /* lane's 4-col base, multiple of 4 */

    // Per-lane precompute: dx^2, column validity (bounds + window + trunc
    // necessary condition dx2<=trunc2 since d2 >= dx2), nearest-x flag.
    float dx2[4];
    bool  xin[4];
    bool  nearx[4];
    bool  anyx = false;
    #pragma unroll
    for (int j = 0; j < 4; ++j) {
        const int   xi = colb + j;
        const float dx = (float)xi - px;
        dx2[j]   = dx * dx;
        nearx[j] = dx2[j] < 0.25f;
        const int w = xi - (cx - RAD);   /* window col index */
        xin[j] = (xi >= 0) && (xi < WW) && (w >= 0) && (w < WIN) && (dx2[j] <= trunc2);
        anyx |= xin[j];
    }

    float* __restrict__ fbase = out + (size_t)f * (HH * WW);
    const int y0 = cy - RAD + rsub;

    #pragma unroll 1
    for (int it = 0; it < 7; ++it) {
        const int r  = rsub + it * 4;    /* window row index, valid < 27 */
        const int yi = y0 + it * 4;
        if (!anyx || r >= WIN || yi < 0 || yi >= HH) continue;

        const float dy  = (float)yi - py;
        const float dy2 = dy * dy;
        if (dy2 > trunc2) continue;      /* whole row truncated for this lane */

        const bool neary = dy2 < 0.25f;
        float vals[4];
        bool  any = false;
        #pragma unroll
        for (int j = 0; j < 4; ++j) {
            const float d2 = dy2 + dx2[j];
            const bool  m  = xin[j] && (d2 <= trunc2);
            float g;
            if (neary && nearx[j]) {
                g = 1.0f;
            } else {
                float t = fmaf(d2, inv8, 1.0f);  /* 1 + x/8 */
                t = t * t;
                t = t * t;
                t = t * t;                       /* (1+x/8)^8 */
                g = t;
            }
            vals[j] = m ? value * g : 0.0f;
            any |= m;
        }
        if (any) {
            /* colb is 4-aligned; WW=400 and HH*WW strides are multiples of 4,
               so the float4 address is 16B-aligned and never straddles a row
               edge (x=0 / x=400 are slot boundaries). OOB components add 0. */
            atomicAdd(reinterpret_cast<float4*>(&fbase[yi * WW + colb]),
                      make_float4(vals[0], vals[1], vals[2], vals[3]));
        }
    }
}

__global__ void __launch_bounds__(256) cifhr_clamp_kernel(float* __restrict__ out)
{
    const int n4 = OUT_ELEMS / 4;
    const int stride = gridDim.x * blockDim.x;
    int i = blockIdx.x * blockDim.x + threadIdx.x;
    float4* o4 = (float4*)out;
    // unroll-4 grid-stride: 4 loads in flight per thread (MLP=4)
    for (; i + 3 * stride < n4; i += 4 * stride) {
        float4 a = o4[i];
        float4 b = o4[i + stride];
        float4 c = o4[i + 2 * stride];
        float4 d = o4[i + 3 * stride];
        a.x = fminf(a.x, 1.0f); a.y = fminf(a.y, 1.0f); a.z = fminf(a.z, 1.0f); a.w = fminf(a.w, 1.0f);
        b.x = fminf(b.x, 1.0f); b.y = fminf(b.y, 1.0f); b.z = fminf(b.z, 1.0f); b.w = fminf(b.w, 1.0f);
        c.x = fminf(c.x, 1.0f); c.y = fminf(c.y, 1.0f); c.z = fminf(c.z, 1.0f); c.w = fminf(c.w, 1.0f);
        d.x = fminf(d.x, 1.0f); d.y = fminf(d.y, 1.0f); d.z = fminf(d.z, 1.0f); d.w = fminf(d.w, 1.0f);
        o4[i] = a;
        o4[i + stride] = b;
        o4[i + 2 * stride] = c;
        o4[i + 3 * stride] = d;
    }
    for (; i < n4; i += stride) {
        float4 a = o4[i];
        a.x = fminf(a.x, 1.0f); a.y = fminf(a.y, 1.0f); a.z = fminf(a.z, 1.0f); a.w = fminf(a.w, 1.0f);
        o4[i] = a;
    }
}

extern "C" void kernel_launch(void* const* d_in, const int* in_sizes, int n_in,
                              void* d_out, int out_size)
{
    const float* cifhr = (const float*)d_in[0];   /* (17,300,400) float32 */
    const float* x     = (const float*)d_in[1];   /* (17,5,38,50)  float32 */
    float* out = (float*)d_out;

    cudaMemcpyAsync(out, cifhr, (size_t)OUT_ELEMS * sizeof(float),
                    cudaMemcpyDeviceToDevice, 0);

    // One warp per point
    const int threads = NPOINTS * 32;
    const int block = 256;
    const int grid = (threads + block - 1) / block;
    cifhr_accum_kernel<<<grid, block, 0, 0>>>(x, out);

    const int n4 = OUT_ELEMS / 4;
    const int cblock = 256;
    const int cgrid = (n4 / 4 + cblock - 1) / cblock;   /* ~498 blocks */
    cifhr_clamp_kernel<<<cgrid, cblock, 0, 0>>>(out);
}